// round 1
// baseline (speedup 1.0000x reference)
#include <cuda_runtime.h>
#include <cstdint>
#include <cstddef>

// Problem constants
#define BB 16384
#define DD 2048
#define HH1 2048
#define HH2 1024
#define PP 512
#define LL 256
#define LRELU_SLOPE 0.01f
#define BN_EPS 1e-5f

// ---------------- device-global scratch (no allocations allowed) ----------------
__device__ float g_h1[(size_t)BB * HH1];   // 134 MB
__device__ float g_h2[(size_t)BB * HH2];   // 67 MB
__device__ float g_nb[PP * LL];
__device__ float g_s1[HH1];
__device__ float g_t1[HH1];
__device__ float g_s2[HH2];
__device__ float g_t2[HH2];

// ---------------- fold BN into per-column scale/shift ----------------
// h = acc + b ; (h - m)*rsqrt(v+eps)*g + be = acc*s + ((b-m)*s + be)
__global__ void prep_scale_kernel(const float* __restrict__ b, const float* __restrict__ g,
                                  const float* __restrict__ be, const float* __restrict__ m,
                                  const float* __restrict__ v, float* __restrict__ s,
                                  float* __restrict__ t, int n) {
    int i = blockIdx.x * blockDim.x + threadIdx.x;
    if (i < n) {
        float sc = g[i] * rsqrtf(v[i] + BN_EPS);
        s[i] = sc;
        t[i] = (b[i] - m[i]) * sc + be[i];
    }
}

// ---------------- basis row-normalization ----------------
__global__ void norm_basis_kernel(const float* __restrict__ basis, float* __restrict__ nb) {
    __shared__ float red[LL];
    int row = blockIdx.x, tid = threadIdx.x;
    float v = basis[row * LL + tid];
    red[tid] = v * v;
    __syncthreads();
    for (int o = LL / 2; o > 0; o >>= 1) {
        if (tid < o) red[tid] += red[tid + o];
        __syncthreads();
    }
    float nrm = sqrtf(red[0]);
    nrm = fmaxf(nrm, 1e-12f);
    nb[row * LL + tid] = v / nrm;
}

// ---------------- SGEMM: C[M,N] = A[M,K] @ B[K,N] (+epilogue) ----------------
// MODE 0: out = leaky_relu(acc * s[col] + t[col])
// MODE 1: out = acc + t[col]      (bias)
// MODE 2: out = acc
// Tiles: 128x128x16, 256 threads, 8x8 per thread, register-prefetch double buffer.
template <int MODE>
__global__ __launch_bounds__(256) void sgemm_kernel(
    const float* __restrict__ A, const float* __restrict__ Bm,
    float* __restrict__ C, int M, int N, int K,
    const float* __restrict__ s, const float* __restrict__ t)
{
    const int BM = 128, BN = 128, BK = 16;
    __shared__ float As[BK][BM];
    __shared__ float Bs[BK][BN];

    int tid  = threadIdx.x;
    int trow = tid >> 4;     // 0..15 (row group of 8)
    int tcol = tid & 15;     // 0..15 (col group of 8)

    size_t aBase = (size_t)blockIdx.y * BM * (size_t)K;
    size_t bCol  = (size_t)blockIdx.x * BN;

    // A tile load mapping: 128 rows x 16 cols, float4 along K
    int aR = tid >> 2;           // 0..63 (+64 on 2nd iter)
    int aC = (tid & 3) * 4;      // 0,4,8,12
    // B tile load mapping: 16 rows x 128 cols, float4 along N
    int bR = tid >> 5;           // 0..7 (+8 on 2nd iter)
    int bC = (tid & 31) * 4;     // 0..124

    float acc[8][8];
#pragma unroll
    for (int m = 0; m < 8; m++)
#pragma unroll
        for (int n = 0; n < 8; n++) acc[m][n] = 0.0f;

    // --- preload tile 0 into smem ---
    {
#pragma unroll
        for (int i = 0; i < 2; i++) {
            int r = aR + i * 64;
            float4 v = *reinterpret_cast<const float4*>(A + aBase + (size_t)r * K + aC);
            As[aC + 0][r] = v.x; As[aC + 1][r] = v.y; As[aC + 2][r] = v.z; As[aC + 3][r] = v.w;
        }
#pragma unroll
        for (int i = 0; i < 2; i++) {
            int r = bR + i * 8;
            float4 v = *reinterpret_cast<const float4*>(Bm + (size_t)r * N + bCol + bC);
            *reinterpret_cast<float4*>(&Bs[r][bC]) = v;
        }
    }
    __syncthreads();

    for (int k0 = 0; k0 < K; k0 += BK) {
        float4 av[2], bv[2];
        bool has_next = (k0 + BK) < K;
        if (has_next) {
            int kn = k0 + BK;
#pragma unroll
            for (int i = 0; i < 2; i++) {
                int r = aR + i * 64;
                av[i] = *reinterpret_cast<const float4*>(A + aBase + (size_t)r * K + kn + aC);
            }
#pragma unroll
            for (int i = 0; i < 2; i++) {
                int r = bR + i * 8;
                bv[i] = *reinterpret_cast<const float4*>(Bm + (size_t)(kn + r) * N + bCol + bC);
            }
        }

#pragma unroll
        for (int kk = 0; kk < BK; kk++) {
            float ar[8], br[8];
#pragma unroll
            for (int m = 0; m < 8; m++) ar[m] = As[kk][trow * 8 + m];
#pragma unroll
            for (int n = 0; n < 8; n++) br[n] = Bs[kk][tcol * 8 + n];
#pragma unroll
            for (int m = 0; m < 8; m++)
#pragma unroll
                for (int n = 0; n < 8; n++) acc[m][n] += ar[m] * br[n];
        }
        __syncthreads();

        if (has_next) {
#pragma unroll
            for (int i = 0; i < 2; i++) {
                int r = aR + i * 64;
                As[aC + 0][r] = av[i].x; As[aC + 1][r] = av[i].y;
                As[aC + 2][r] = av[i].z; As[aC + 3][r] = av[i].w;
            }
#pragma unroll
            for (int i = 0; i < 2; i++) {
                int r = bR + i * 8;
                *reinterpret_cast<float4*>(&Bs[r][bC]) = bv[i];
            }
            __syncthreads();
        }
    }

    // --- epilogue ---
    float sc[8], tc[8];
    if (MODE == 0) {
#pragma unroll
        for (int n = 0; n < 8; n++) {
            sc[n] = s[bCol + tcol * 8 + n];
            tc[n] = t[bCol + tcol * 8 + n];
        }
    } else if (MODE == 1) {
#pragma unroll
        for (int n = 0; n < 8; n++) tc[n] = t[bCol + tcol * 8 + n];
    }

#pragma unroll
    for (int m = 0; m < 8; m++) {
        size_t r = (size_t)blockIdx.y * BM + trow * 8 + m;
        float out[8];
#pragma unroll
        for (int n = 0; n < 8; n++) {
            float v = acc[m][n];
            if (MODE == 0) {
                v = v * sc[n] + tc[n];
                v = (v >= 0.0f) ? v : LRELU_SLOPE * v;
            } else if (MODE == 1) {
                v += tc[n];
            }
            out[n] = v;
        }
        float* Crow = C + r * N + bCol + tcol * 8;
        *reinterpret_cast<float4*>(Crow)     = make_float4(out[0], out[1], out[2], out[3]);
        *reinterpret_cast<float4*>(Crow + 4) = make_float4(out[4], out[5], out[6], out[7]);
    }
}

// ---------------- sparsemax over rows of length P=512 ----------------
// Matches reference: z = logits - max; sort desc; cumsum; support count;
// tau = (cs[ss-1]-1)/ss; a = clip(z - tau, 0); a /= max(sum(a), 1e-8).
__global__ __launch_bounds__(PP) void sparsemax_kernel(const float* __restrict__ logits,
                                                       float* __restrict__ a) {
    __shared__ float z[PP];
    __shared__ float zs[PP];
    __shared__ float cs[PP];
    __shared__ float red[PP];
    __shared__ int redi[PP];

    int row = blockIdx.x, tid = threadIdx.x;
    float v = logits[(size_t)row * PP + tid];

    // row max
    red[tid] = v;
    __syncthreads();
    for (int o = PP / 2; o > 0; o >>= 1) {
        if (tid < o) red[tid] = fmaxf(red[tid], red[tid + o]);
        __syncthreads();
    }
    float zmax = red[0];
    __syncthreads();

    float zi = v - zmax;
    z[tid] = zi;
    zs[tid] = zi;
    __syncthreads();

    // bitonic sort descending (512 elems, 512 threads)
    for (int k = 2; k <= PP; k <<= 1) {
        for (int j = k >> 1; j > 0; j >>= 1) {
            int ixj = tid ^ j;
            if (ixj > tid) {
                float x0 = zs[tid], x1 = zs[ixj];
                bool desc = ((tid & k) == 0);
                if ((x0 < x1) == desc) { zs[tid] = x1; zs[ixj] = x0; }
            }
            __syncthreads();
        }
    }

    // inclusive scan (Hillis-Steele)
    cs[tid] = zs[tid];
    __syncthreads();
    for (int o = 1; o < PP; o <<= 1) {
        float prev = (tid >= o) ? cs[tid - o] : 0.0f;
        float cur = cs[tid];
        __syncthreads();
        cs[tid] = cur + prev;
        __syncthreads();
    }

    // support size
    redi[tid] = (1.0f + (float)(tid + 1) * zs[tid] > cs[tid]) ? 1 : 0;
    __syncthreads();
    for (int o = PP / 2; o > 0; o >>= 1) {
        if (tid < o) redi[tid] += redi[tid + o];
        __syncthreads();
    }
    int ss = redi[0];
    if (ss < 1) ss = 1;
    float tau = (cs[ss - 1] - 1.0f) / (float)ss;

    float ai = zi - tau;
    ai = (ai > 0.0f) ? ai : 0.0f;

    // row sum + renormalize
    red[tid] = ai;
    __syncthreads();
    for (int o = PP / 2; o > 0; o >>= 1) {
        if (tid < o) red[tid] += red[tid + o];
        __syncthreads();
    }
    float ssum = red[0];
    ssum = (ssum > 1e-8f) ? ssum : 1e-8f;
    a[(size_t)row * PP + tid] = ai / ssum;
}

// ---------------- launch ----------------
extern "C" void kernel_launch(void* const* d_in, const int* in_sizes, int n_in,
                              void* d_out, int out_size) {
    const float* x   = (const float*)d_in[0];
    const float* W1  = (const float*)d_in[1];
    const float* b1  = (const float*)d_in[2];
    const float* g1  = (const float*)d_in[3];
    const float* be1 = (const float*)d_in[4];
    const float* m1  = (const float*)d_in[5];
    const float* v1  = (const float*)d_in[6];
    const float* W2  = (const float*)d_in[7];
    const float* b2  = (const float*)d_in[8];
    const float* g2  = (const float*)d_in[9];
    const float* be2 = (const float*)d_in[10];
    const float* m2  = (const float*)d_in[11];
    const float* v2  = (const float*)d_in[12];
    const float* Wl  = (const float*)d_in[13];
    const float* bl  = (const float*)d_in[14];
    const float* basis = (const float*)d_in[15];

    float* out = (float*)d_out;
    float* a_out      = out;                                   // [B, P]
    float* z_out      = out + (size_t)BB * PP;                 // [B, L]
    float* logits_out = out + (size_t)BB * PP + (size_t)BB * LL; // [B, P]

    float *h1, *h2, *nb, *s1, *t1, *s2, *t2;
    cudaGetSymbolAddress((void**)&h1, g_h1);
    cudaGetSymbolAddress((void**)&h2, g_h2);
    cudaGetSymbolAddress((void**)&nb, g_nb);
    cudaGetSymbolAddress((void**)&s1, g_s1);
    cudaGetSymbolAddress((void**)&t1, g_t1);
    cudaGetSymbolAddress((void**)&s2, g_s2);
    cudaGetSymbolAddress((void**)&t2, g_t2);

    // BN folds + basis normalization (tiny)
    prep_scale_kernel<<<(HH1 + 255) / 256, 256>>>(b1, g1, be1, m1, v1, s1, t1, HH1);
    prep_scale_kernel<<<(HH2 + 255) / 256, 256>>>(b2, g2, be2, m2, v2, s2, t2, HH2);
    norm_basis_kernel<<<PP, LL>>>(basis, nb);

    // Layer 1: h1 = lrelu(BN(x @ W1 + b1))
    sgemm_kernel<0><<<dim3(HH1 / 128, BB / 128), 256>>>(x, W1, h1, BB, HH1, DD, s1, t1);
    // Layer 2: h2 = lrelu(BN(h1 @ W2 + b2))
    sgemm_kernel<0><<<dim3(HH2 / 128, BB / 128), 256>>>(h1, W2, h2, BB, HH2, HH1, s2, t2);
    // logits = h2 @ Wl + bl  (written straight into output slot)
    sgemm_kernel<1><<<dim3(PP / 128, BB / 128), 256>>>(h2, Wl, logits_out, BB, PP, HH2, nullptr, bl);
    // a = renormalized sparsemax(logits)
    sparsemax_kernel<<<BB, PP>>>(logits_out, a_out);
    // z_bio = a @ nb
    sgemm_kernel<2><<<dim3(LL / 128, BB / 128), 256>>>(a_out, nb, z_out, BB, LL, PP, nullptr, nullptr);
}

// round 5
// speedup vs baseline: 2.2073x; 2.2073x over previous
#include <cuda_runtime.h>
#include <cuda_bf16.h>
#include <cstdint>
#include <cstddef>

// Problem constants
#define BB 16384
#define DD 2048
#define HH1 2048
#define HH2 1024
#define PP 512
#define LL 256
#define LRELU_SLOPE 0.01f
#define BN_EPS 1e-5f

// ---------------- device-global scratch ----------------
__device__ __nv_bfloat16 g_xhi[(size_t)BB * DD];
__device__ __nv_bfloat16 g_xlo[(size_t)BB * DD];
__device__ __nv_bfloat16 g_h1hi[(size_t)BB * HH1];
__device__ __nv_bfloat16 g_h1lo[(size_t)BB * HH1];
__device__ __nv_bfloat16 g_h2hi[(size_t)BB * HH2];
__device__ __nv_bfloat16 g_h2lo[(size_t)BB * HH2];
__device__ __nv_bfloat16 g_ahi[(size_t)BB * PP];
__device__ __nv_bfloat16 g_alo[(size_t)BB * PP];
__device__ __nv_bfloat16 g_w1thi[(size_t)HH1 * DD];
__device__ __nv_bfloat16 g_w1tlo[(size_t)HH1 * DD];
__device__ __nv_bfloat16 g_w2thi[(size_t)HH2 * HH1];
__device__ __nv_bfloat16 g_w2tlo[(size_t)HH2 * HH1];
__device__ __nv_bfloat16 g_wlthi[(size_t)PP * HH2];
__device__ __nv_bfloat16 g_wltlo[(size_t)PP * HH2];
__device__ __nv_bfloat16 g_nbthi[(size_t)LL * PP];
__device__ __nv_bfloat16 g_nbtlo[(size_t)LL * PP];
__device__ float g_s1[HH1];
__device__ float g_t1[HH1];
__device__ float g_s2[HH2];
__device__ float g_t2[HH2];

// ---------------- helpers ----------------
__device__ __forceinline__ uint32_t smem_u32(const void* p) {
    uint32_t a;
    asm("{ .reg .u64 t; cvta.to.shared.u64 t, %1; cvt.u32.u64 %0, t; }" : "=r"(a) : "l"(p));
    return a;
}

__device__ __forceinline__ void cpasync16(uint32_t dst, const void* src) {
    asm volatile("cp.async.cg.shared.global [%0], [%1], 16;" :: "r"(dst), "l"(src));
}
#define CP_COMMIT() asm volatile("cp.async.commit_group;" ::: "memory")

__device__ __forceinline__ void ldsm4(uint32_t& r0, uint32_t& r1, uint32_t& r2, uint32_t& r3,
                                      uint32_t addr) {
    asm volatile("ldmatrix.sync.aligned.m8n8.x4.shared.b16 {%0,%1,%2,%3}, [%4];"
                 : "=r"(r0), "=r"(r1), "=r"(r2), "=r"(r3) : "r"(addr));
}

__device__ __forceinline__ void mma16816(float* c, const uint32_t* a, const uint32_t* b) {
    asm volatile(
        "mma.sync.aligned.m16n8k16.row.col.f32.bf16.bf16.f32 "
        "{%0,%1,%2,%3}, {%4,%5,%6,%7}, {%8,%9}, {%0,%1,%2,%3};"
        : "+f"(c[0]), "+f"(c[1]), "+f"(c[2]), "+f"(c[3])
        : "r"(a[0]), "r"(a[1]), "r"(a[2]), "r"(a[3]), "r"(b[0]), "r"(b[1]));
}

__device__ __forceinline__ void split_bf(float v, __nv_bfloat16& hi, __nv_bfloat16& lo) {
    hi = __float2bfloat16(v);
    lo = __float2bfloat16(v - __bfloat162float(hi));
}

// ---------------- prep kernels ----------------
__global__ void prep_scale_kernel(const float* __restrict__ b, const float* __restrict__ g,
                                  const float* __restrict__ be, const float* __restrict__ m,
                                  const float* __restrict__ v, float* __restrict__ s,
                                  float* __restrict__ t, int n) {
    int i = blockIdx.x * blockDim.x + threadIdx.x;
    if (i < n) {
        float sc = g[i] * rsqrtf(v[i] + BN_EPS);
        s[i] = sc;
        t[i] = (b[i] - m[i]) * sc + be[i];
    }
}

__global__ void split_kernel(const float* __restrict__ x, __nv_bfloat16* __restrict__ hi,
                             __nv_bfloat16* __restrict__ lo, size_t n4) {
    size_t i = (size_t)blockIdx.x * blockDim.x + threadIdx.x;
    if (i < n4) {
        float4 v = reinterpret_cast<const float4*>(x)[i];
        __nv_bfloat16 h[4], l[4];
        split_bf(v.x, h[0], l[0]);
        split_bf(v.y, h[1], l[1]);
        split_bf(v.z, h[2], l[2]);
        split_bf(v.w, h[3], l[3]);
        reinterpret_cast<uint2*>(hi)[i] = *reinterpret_cast<uint2*>(h);
        reinterpret_cast<uint2*>(lo)[i] = *reinterpret_cast<uint2*>(l);
    }
}

// transpose [K,N] fp32 -> [N,K] bf16 hi/lo
__global__ void transpose_split_kernel(const float* __restrict__ W, __nv_bfloat16* __restrict__ hi,
                                       __nv_bfloat16* __restrict__ lo, int K, int N) {
    __shared__ float tile[32][33];
    int n0 = blockIdx.x * 32, k0 = blockIdx.y * 32;
    int tx = threadIdx.x, ty = threadIdx.y;
#pragma unroll
    for (int i = 0; i < 32; i += 8)
        tile[ty + i][tx] = W[(size_t)(k0 + ty + i) * N + n0 + tx];
    __syncthreads();
#pragma unroll
    for (int i = 0; i < 32; i += 8) {
        float v = tile[tx][ty + i];
        size_t o = (size_t)(n0 + ty + i) * K + k0 + tx;
        __nv_bfloat16 h, l;
        split_bf(v, h, l);
        hi[o] = h;
        lo[o] = l;
    }
}

// normalize basis rows + transpose -> nbt [L, P] bf16 hi/lo
__global__ void nbt_kernel(const float* __restrict__ basis, __nv_bfloat16* __restrict__ hi,
                           __nv_bfloat16* __restrict__ lo) {
    __shared__ float red[LL];
    int p = blockIdx.x, l = threadIdx.x;
    float v = basis[(size_t)p * LL + l];
    red[l] = v * v;
    __syncthreads();
    for (int o = LL / 2; o > 0; o >>= 1) {
        if (l < o) red[l] += red[l + o];
        __syncthreads();
    }
    float nrm = fmaxf(sqrtf(red[0]), 1e-12f);
    float nv = v / nrm;
    __nv_bfloat16 h, lw;
    split_bf(nv, h, lw);
    size_t o = (size_t)l * PP + p;
    hi[o] = h;
    lo[o] = lw;
}

// ---------------- mma.sync GEMM ----------------
// C[M, Ntot] = (Ahi+Alo)[M,K] @ (Bhi+Blo)[Ntot,K]^T ; bf16x3 split, fp32 acc.
// CTA tile 128x128, K-chunk 64. 8 warps (4x2), warp tile 32x64.
// SMEM per stage: Ahi|Alo|Bhi|Blo each 128x64 bf16 = 16KB -> 64KB; 2 stages.
// Rows are 128B (64 bf16); chunk swizzle: 16B chunk c stored at c ^ (row & 7).
#define TILE_B 16384
#define STAGE_B 65536
#define SMEM_TOTAL (128 + 2 * STAGE_B)

template <int MODE>
__global__ __launch_bounds__(256, 1) void mma_gemm_kernel(
    const __nv_bfloat16* __restrict__ Ahi, const __nv_bfloat16* __restrict__ Alo,
    const __nv_bfloat16* __restrict__ Bhi, const __nv_bfloat16* __restrict__ Blo,
    int K, int Ntot,
    const float* __restrict__ s, const float* __restrict__ t,
    float* __restrict__ Cf, __nv_bfloat16* __restrict__ Chi, __nv_bfloat16* __restrict__ Clo)
{
    extern __shared__ char smem_raw[];
    uint32_t sb = (smem_u32(smem_raw) + 127u) & ~127u;

    const int tid = threadIdx.x;
    const int lane = tid & 31;
    const int warp = tid >> 5;
    const int warpM = (warp & 3) * 32;
    const int warpN = (warp >> 2) * 64;

    const int rowA0 = blockIdx.y * 128;
    const int rowB0 = blockIdx.x * 128;
    const int nch = K >> 6;

    // cp.async mapping: 1024 16B-chunks per tile, 4 per thread
    const int ldR = tid >> 1;                // row 0..127 (2 threads per row)
    const int ldC0 = (tid & 1) * 4;          // chunk 0..3 or 4..7 base

    // ldmatrix lane mapping
    const int g = lane >> 3, r8 = lane & 7;
    const int mA = warpM + ((g & 1) << 3) + r8;   // + mt*16
    const int cAg = g >> 1;
    const int swzA = mA & 7;
    const int nB = warpN + ((g >> 1) << 3) + r8;  // + ng*16
    const int cBg = g & 1;
    const int swzB = nB & 7;

    float acc[2][8][4];
#pragma unroll
    for (int mt = 0; mt < 2; mt++)
#pragma unroll
        for (int nt = 0; nt < 8; nt++)
#pragma unroll
            for (int i = 0; i < 4; i++) acc[mt][nt][i] = 0.0f;

    // load one stage (4 tiles) — each thread 16 cp.asyncs
    auto load_stage = [&](int stage, int k0) {
        uint32_t st = sb + (uint32_t)stage * STAGE_B;
        const __nv_bfloat16* srcs[4] = {Ahi, Alo, Bhi, Blo};
#pragma unroll
        for (int tidx = 0; tidx < 4; tidx++) {
            const __nv_bfloat16* base = srcs[tidx];
            int row0 = (tidx < 2) ? rowA0 : rowB0;
            uint32_t tb = st + (uint32_t)tidx * TILE_B;
#pragma unroll
            for (int c = 0; c < 4; c++) {
                int ch = ldC0 + c;
                const __nv_bfloat16* src = base + (size_t)(row0 + ldR) * K + (k0 + ch * 8);
                uint32_t dst = tb + (uint32_t)(ldR * 128 + ((ch ^ (ldR & 7)) << 4));
                cpasync16(dst, src);
            }
        }
    };

    load_stage(0, 0);
    CP_COMMIT();

    for (int ck = 0; ck < nch; ck++) {
        if (ck + 1 < nch) {
            load_stage((ck + 1) & 1, (ck + 1) << 6);
            CP_COMMIT();
            asm volatile("cp.async.wait_group 1;" ::: "memory");
        } else {
            asm volatile("cp.async.wait_group 0;" ::: "memory");
        }
        __syncthreads();

        uint32_t stA_hi = sb + (uint32_t)(ck & 1) * STAGE_B;
        uint32_t stA_lo = stA_hi + TILE_B;
        uint32_t stB_hi = stA_hi + 2 * TILE_B;
        uint32_t stB_lo = stA_hi + 3 * TILE_B;

#pragma unroll
        for (int ks = 0; ks < 4; ks++) {
            uint32_t ah[2][4], al[2][4], bh[4][4], bl[4][4];
#pragma unroll
            for (int mt = 0; mt < 2; mt++) {
                uint32_t roff = (uint32_t)((mA + mt * 16) * 128 +
                                           ((((ks << 1) + cAg) ^ swzA) << 4));
                ldsm4(ah[mt][0], ah[mt][1], ah[mt][2], ah[mt][3], stA_hi + roff);
                ldsm4(al[mt][0], al[mt][1], al[mt][2], al[mt][3], stA_lo + roff);
            }
#pragma unroll
            for (int ng = 0; ng < 4; ng++) {
                uint32_t roff = (uint32_t)((nB + ng * 16) * 128 +
                                           ((((ks << 1) + cBg) ^ swzB) << 4));
                ldsm4(bh[ng][0], bh[ng][1], bh[ng][2], bh[ng][3], stB_hi + roff);
                ldsm4(bl[ng][0], bl[ng][1], bl[ng][2], bl[ng][3], stB_lo + roff);
            }
#pragma unroll
            for (int mt = 0; mt < 2; mt++)
#pragma unroll
                for (int nt = 0; nt < 8; nt++) {
                    const uint32_t* bph = &bh[nt >> 1][(nt & 1) << 1];
                    const uint32_t* bpl = &bl[nt >> 1][(nt & 1) << 1];
                    mma16816(acc[mt][nt], ah[mt], bph);
                    mma16816(acc[mt][nt], ah[mt], bpl);
                    mma16816(acc[mt][nt], al[mt], bph);
                }
        }
        __syncthreads();
    }

    // ---- epilogue ----
    const int gid = lane >> 2, tig = lane & 3;
#pragma unroll
    for (int mt = 0; mt < 2; mt++) {
        int row0 = rowA0 + warpM + mt * 16 + gid;
#pragma unroll
        for (int nt = 0; nt < 8; nt++) {
            int n0 = rowB0 + warpN + nt * 8 + tig * 2;
            float c0 = acc[mt][nt][0], c1 = acc[mt][nt][1];
            float c2 = acc[mt][nt][2], c3 = acc[mt][nt][3];
            if (MODE == 0) {
                float s0 = s[n0], s1v = s[n0 + 1], t0 = t[n0], t1v = t[n0 + 1];
                float v0 = c0 * s0 + t0; v0 = (v0 >= 0.f) ? v0 : LRELU_SLOPE * v0;
                float v1 = c1 * s1v + t1v; v1 = (v1 >= 0.f) ? v1 : LRELU_SLOPE * v1;
                float v2 = c2 * s0 + t0; v2 = (v2 >= 0.f) ? v2 : LRELU_SLOPE * v2;
                float v3 = c3 * s1v + t1v; v3 = (v3 >= 0.f) ? v3 : LRELU_SLOPE * v3;
                __nv_bfloat16 h0, l0, h1, l1;
                split_bf(v0, h0, l0); split_bf(v1, h1, l1);
                __nv_bfloat162 hp; hp.x = h0; hp.y = h1;
                __nv_bfloat162 lp; lp.x = l0; lp.y = l1;
                *reinterpret_cast<__nv_bfloat162*>(Chi + (size_t)row0 * Ntot + n0) = hp;
                *reinterpret_cast<__nv_bfloat162*>(Clo + (size_t)row0 * Ntot + n0) = lp;
                split_bf(v2, h0, l0); split_bf(v3, h1, l1);
                hp.x = h0; hp.y = h1; lp.x = l0; lp.y = l1;
                *reinterpret_cast<__nv_bfloat162*>(Chi + (size_t)(row0 + 8) * Ntot + n0) = hp;
                *reinterpret_cast<__nv_bfloat162*>(Clo + (size_t)(row0 + 8) * Ntot + n0) = lp;
            } else {
                if (MODE == 1) {
                    float t0 = t[n0], t1v = t[n0 + 1];
                    c0 += t0; c1 += t1v; c2 += t0; c3 += t1v;
                }
                *reinterpret_cast<float2*>(Cf + (size_t)row0 * Ntot + n0) = make_float2(c0, c1);
                *reinterpret_cast<float2*>(Cf + (size_t)(row0 + 8) * Ntot + n0) = make_float2(c2, c3);
            }
        }
    }
}

// ---------------- sparsemax (P=512 per row) + split-bf16 output ----------------
__global__ __launch_bounds__(PP) void sparsemax_kernel(const float* __restrict__ logits,
                                                       float* __restrict__ a,
                                                       __nv_bfloat16* __restrict__ ahi,
                                                       __nv_bfloat16* __restrict__ alo) {
    __shared__ float zs[PP];
    __shared__ float cs[PP];
    __shared__ float red[PP];
    __shared__ int redi[PP];

    int row = blockIdx.x, tid = threadIdx.x;
    float v = logits[(size_t)row * PP + tid];

    red[tid] = v;
    __syncthreads();
    for (int o = PP / 2; o > 0; o >>= 1) {
        if (tid < o) red[tid] = fmaxf(red[tid], red[tid + o]);
        __syncthreads();
    }
    float zmax = red[0];
    __syncthreads();

    float zi = v - zmax;
    zs[tid] = zi;
    __syncthreads();

    for (int k = 2; k <= PP; k <<= 1) {
        for (int j = k >> 1; j > 0; j >>= 1) {
            int ixj = tid ^ j;
            if (ixj > tid) {
                float x0 = zs[tid], x1 = zs[ixj];
                bool desc = ((tid & k) == 0);
                if ((x0 < x1) == desc) { zs[tid] = x1; zs[ixj] = x0; }
            }
            __syncthreads();
        }
    }

    cs[tid] = zs[tid];
    __syncthreads();
    for (int o = 1; o < PP; o <<= 1) {
        float prev = (tid >= o) ? cs[tid - o] : 0.0f;
        float cur = cs[tid];
        __syncthreads();
        cs[tid] = cur + prev;
        __syncthreads();
    }

    redi[tid] = (1.0f + (float)(tid + 1) * zs[tid] > cs[tid]) ? 1 : 0;
    __syncthreads();
    for (int o = PP / 2; o > 0; o >>= 1) {
        if (tid < o) redi[tid] += redi[tid + o];
        __syncthreads();
    }
    int ssn = redi[0];
    if (ssn < 1) ssn = 1;
    float tau = (cs[ssn - 1] - 1.0f) / (float)ssn;

    float ai = zi - tau;
    ai = (ai > 0.0f) ? ai : 0.0f;

    red[tid] = ai;
    __syncthreads();
    for (int o = PP / 2; o > 0; o >>= 1) {
        if (tid < o) red[tid] += red[tid + o];
        __syncthreads();
    }
    float ssum = red[0];
    ssum = (ssum > 1e-8f) ? ssum : 1e-8f;
    float av = ai / ssum;
    size_t idx = (size_t)row * PP + tid;
    a[idx] = av;
    __nv_bfloat16 h, l;
    split_bf(av, h, l);
    ahi[idx] = h;
    alo[idx] = l;
}

// ---------------- launch ----------------
extern "C" void kernel_launch(void* const* d_in, const int* in_sizes, int n_in,
                              void* d_out, int out_size) {
    const float* x   = (const float*)d_in[0];
    const float* W1  = (const float*)d_in[1];
    const float* b1  = (const float*)d_in[2];
    const float* g1  = (const float*)d_in[3];
    const float* be1 = (const float*)d_in[4];
    const float* m1  = (const float*)d_in[5];
    const float* v1  = (const float*)d_in[6];
    const float* W2  = (const float*)d_in[7];
    const float* b2  = (const float*)d_in[8];
    const float* g2  = (const float*)d_in[9];
    const float* be2 = (const float*)d_in[10];
    const float* m2  = (const float*)d_in[11];
    const float* v2  = (const float*)d_in[12];
    const float* Wl  = (const float*)d_in[13];
    const float* bl  = (const float*)d_in[14];
    const float* basis = (const float*)d_in[15];

    float* out = (float*)d_out;
    float* a_out      = out;
    float* z_out      = out + (size_t)BB * PP;
    float* logits_out = out + (size_t)BB * PP + (size_t)BB * LL;

    __nv_bfloat16 *xhi, *xlo, *h1hi, *h1lo, *h2hi, *h2lo, *ahi, *alo;
    __nv_bfloat16 *w1thi, *w1tlo, *w2thi, *w2tlo, *wlthi, *wltlo, *nbthi, *nbtlo;
    float *s1, *t1, *s2, *t2;
    cudaGetSymbolAddress((void**)&xhi, g_xhi);
    cudaGetSymbolAddress((void**)&xlo, g_xlo);
    cudaGetSymbolAddress((void**)&h1hi, g_h1hi);
    cudaGetSymbolAddress((void**)&h1lo, g_h1lo);
    cudaGetSymbolAddress((void**)&h2hi, g_h2hi);
    cudaGetSymbolAddress((void**)&h2lo, g_h2lo);
    cudaGetSymbolAddress((void**)&ahi, g_ahi);
    cudaGetSymbolAddress((void**)&alo, g_alo);
    cudaGetSymbolAddress((void**)&w1thi, g_w1thi);
    cudaGetSymbolAddress((void**)&w1tlo, g_w1tlo);
    cudaGetSymbolAddress((void**)&w2thi, g_w2thi);
    cudaGetSymbolAddress((void**)&w2tlo, g_w2tlo);
    cudaGetSymbolAddress((void**)&wlthi, g_wlthi);
    cudaGetSymbolAddress((void**)&wltlo, g_wltlo);
    cudaGetSymbolAddress((void**)&nbthi, g_nbthi);
    cudaGetSymbolAddress((void**)&nbtlo, g_nbtlo);
    cudaGetSymbolAddress((void**)&s1, g_s1);
    cudaGetSymbolAddress((void**)&t1, g_t1);
    cudaGetSymbolAddress((void**)&s2, g_s2);
    cudaGetSymbolAddress((void**)&t2, g_t2);

    cudaFuncSetAttribute(mma_gemm_kernel<0>, cudaFuncAttributeMaxDynamicSharedMemorySize, SMEM_TOTAL);
    cudaFuncSetAttribute(mma_gemm_kernel<1>, cudaFuncAttributeMaxDynamicSharedMemorySize, SMEM_TOTAL);
    cudaFuncSetAttribute(mma_gemm_kernel<2>, cudaFuncAttributeMaxDynamicSharedMemorySize, SMEM_TOTAL);

    // prep
    prep_scale_kernel<<<(HH1 + 255) / 256, 256>>>(b1, g1, be1, m1, v1, s1, t1, HH1);
    prep_scale_kernel<<<(HH2 + 255) / 256, 256>>>(b2, g2, be2, m2, v2, s2, t2, HH2);
    transpose_split_kernel<<<dim3(HH1 / 32, DD / 32), dim3(32, 8)>>>(W1, w1thi, w1tlo, DD, HH1);
    transpose_split_kernel<<<dim3(HH2 / 32, HH1 / 32), dim3(32, 8)>>>(W2, w2thi, w2tlo, HH1, HH2);
    transpose_split_kernel<<<dim3(PP / 32, HH2 / 32), dim3(32, 8)>>>(Wl, wlthi, wltlo, HH2, PP);
    nbt_kernel<<<PP, LL>>>(basis, nbthi, nbtlo);
    {
        size_t n4 = (size_t)BB * DD / 4;
        split_kernel<<<(unsigned)((n4 + 255) / 256), 256>>>(x, xhi, xlo, n4);
    }

    // GEMM 1: h1 = lrelu(BN(x @ W1))
    mma_gemm_kernel<0><<<dim3(HH1 / 128, BB / 128), 256, SMEM_TOTAL>>>(
        xhi, xlo, w1thi, w1tlo, DD, HH1, s1, t1, nullptr, h1hi, h1lo);
    // GEMM 2: h2 = lrelu(BN(h1 @ W2))
    mma_gemm_kernel<0><<<dim3(HH2 / 128, BB / 128), 256, SMEM_TOTAL>>>(
        h1hi, h1lo, w2thi, w2tlo, HH1, HH2, s2, t2, nullptr, h2hi, h2lo);
    // GEMM 3: logits = h2 @ Wl + bl
    mma_gemm_kernel<1><<<dim3(PP / 128, BB / 128), 256, SMEM_TOTAL>>>(
        h2hi, h2lo, wlthi, wltlo, HH2, PP, nullptr, bl, logits_out, nullptr, nullptr);
    // sparsemax
    sparsemax_kernel<<<BB, PP>>>(logits_out, a_out, ahi, alo);
    // GEMM 4: z = a @ nb
    mma_gemm_kernel<2><<<dim3(LL / 128, BB / 128), 256, SMEM_TOTAL>>>(
        ahi, alo, nbthi, nbtlo, PP, LL, nullptr, nullptr, z_out, nullptr, nullptr);
}

// round 6
// speedup vs baseline: 2.2237x; 1.0074x over previous
#include <cuda_runtime.h>
#include <cuda_bf16.h>
#include <cstdint>
#include <cstddef>

// Problem constants
#define BB 16384
#define DD 2048
#define HH1 2048
#define HH2 1024
#define PP 512
#define LL 256
#define LRELU_SLOPE 0.01f
#define BN_EPS 1e-5f

// ---------------- device-global scratch ----------------
__device__ __nv_bfloat16 g_xhi[(size_t)BB * DD];
__device__ __nv_bfloat16 g_xlo[(size_t)BB * DD];
__device__ __nv_bfloat16 g_h1hi[(size_t)BB * HH1];
__device__ __nv_bfloat16 g_h1lo[(size_t)BB * HH1];
__device__ __nv_bfloat16 g_h2hi[(size_t)BB * HH2];
__device__ __nv_bfloat16 g_h2lo[(size_t)BB * HH2];
__device__ __nv_bfloat16 g_ahi[(size_t)BB * PP];
__device__ __nv_bfloat16 g_alo[(size_t)BB * PP];
__device__ __nv_bfloat16 g_w1thi[(size_t)HH1 * DD];
__device__ __nv_bfloat16 g_w1tlo[(size_t)HH1 * DD];
__device__ __nv_bfloat16 g_w2thi[(size_t)HH2 * HH1];
__device__ __nv_bfloat16 g_w2tlo[(size_t)HH2 * HH1];
__device__ __nv_bfloat16 g_wlthi[(size_t)PP * HH2];
__device__ __nv_bfloat16 g_wltlo[(size_t)PP * HH2];
__device__ __nv_bfloat16 g_nbthi[(size_t)LL * PP];
__device__ __nv_bfloat16 g_nbtlo[(size_t)LL * PP];
__device__ float g_s1[HH1];
__device__ float g_t1[HH1];
__device__ float g_s2[HH2];
__device__ float g_t2[HH2];

// ---------------- helpers ----------------
__device__ __forceinline__ uint32_t smem_u32(const void* p) {
    uint32_t a;
    asm("{ .reg .u64 t; cvta.to.shared.u64 t, %1; cvt.u32.u64 %0, t; }" : "=r"(a) : "l"(p));
    return a;
}

__device__ __forceinline__ void cpasync16(uint32_t dst, const void* src) {
    asm volatile("cp.async.cg.shared.global [%0], [%1], 16;" :: "r"(dst), "l"(src));
}
#define CP_COMMIT() asm volatile("cp.async.commit_group;" ::: "memory")

__device__ __forceinline__ void ldsm4(uint32_t& r0, uint32_t& r1, uint32_t& r2, uint32_t& r3,
                                      uint32_t addr) {
    asm volatile("ldmatrix.sync.aligned.m8n8.x4.shared.b16 {%0,%1,%2,%3}, [%4];"
                 : "=r"(r0), "=r"(r1), "=r"(r2), "=r"(r3) : "r"(addr));
}

__device__ __forceinline__ void mma16816(float* c, const uint32_t* a, const uint32_t* b) {
    asm volatile(
        "mma.sync.aligned.m16n8k16.row.col.f32.bf16.bf16.f32 "
        "{%0,%1,%2,%3}, {%4,%5,%6,%7}, {%8,%9}, {%0,%1,%2,%3};"
        : "+f"(c[0]), "+f"(c[1]), "+f"(c[2]), "+f"(c[3])
        : "r"(a[0]), "r"(a[1]), "r"(a[2]), "r"(a[3]), "r"(b[0]), "r"(b[1]));
}

__device__ __forceinline__ void split_bf(float v, __nv_bfloat16& hi, __nv_bfloat16& lo) {
    hi = __float2bfloat16(v);
    lo = __float2bfloat16(v - __bfloat162float(hi));
}

// ---------------- prep kernels ----------------
__global__ void prep_scale_kernel(const float* __restrict__ b, const float* __restrict__ g,
                                  const float* __restrict__ be, const float* __restrict__ m,
                                  const float* __restrict__ v, float* __restrict__ s,
                                  float* __restrict__ t, int n) {
    int i = blockIdx.x * blockDim.x + threadIdx.x;
    if (i < n) {
        float sc = g[i] * rsqrtf(v[i] + BN_EPS);
        s[i] = sc;
        t[i] = (b[i] - m[i]) * sc + be[i];
    }
}

__global__ void split_kernel(const float* __restrict__ x, __nv_bfloat16* __restrict__ hi,
                             __nv_bfloat16* __restrict__ lo, size_t n4) {
    size_t i = (size_t)blockIdx.x * blockDim.x + threadIdx.x;
    if (i < n4) {
        float4 v = reinterpret_cast<const float4*>(x)[i];
        __nv_bfloat16 h[4], l[4];
        split_bf(v.x, h[0], l[0]);
        split_bf(v.y, h[1], l[1]);
        split_bf(v.z, h[2], l[2]);
        split_bf(v.w, h[3], l[3]);
        reinterpret_cast<uint2*>(hi)[i] = *reinterpret_cast<uint2*>(h);
        reinterpret_cast<uint2*>(lo)[i] = *reinterpret_cast<uint2*>(l);
    }
}

// transpose [K,N] fp32 -> [N,K] bf16 hi/lo
__global__ void transpose_split_kernel(const float* __restrict__ W, __nv_bfloat16* __restrict__ hi,
                                       __nv_bfloat16* __restrict__ lo, int K, int N) {
    __shared__ float tile[32][33];
    int n0 = blockIdx.x * 32, k0 = blockIdx.y * 32;
    int tx = threadIdx.x, ty = threadIdx.y;
#pragma unroll
    for (int i = 0; i < 32; i += 8)
        tile[ty + i][tx] = W[(size_t)(k0 + ty + i) * N + n0 + tx];
    __syncthreads();
#pragma unroll
    for (int i = 0; i < 32; i += 8) {
        float v = tile[tx][ty + i];
        size_t o = (size_t)(n0 + ty + i) * K + k0 + tx;
        __nv_bfloat16 h, l;
        split_bf(v, h, l);
        hi[o] = h;
        lo[o] = l;
    }
}

// normalize basis rows + transpose -> nbt [L, P] bf16 hi/lo
__global__ void nbt_kernel(const float* __restrict__ basis, __nv_bfloat16* __restrict__ hi,
                           __nv_bfloat16* __restrict__ lo) {
    __shared__ float red[LL];
    int p = blockIdx.x, l = threadIdx.x;
    float v = basis[(size_t)p * LL + l];
    red[l] = v * v;
    __syncthreads();
    for (int o = LL / 2; o > 0; o >>= 1) {
        if (l < o) red[l] += red[l + o];
        __syncthreads();
    }
    float nrm = fmaxf(sqrtf(red[0]), 1e-12f);
    float nv = v / nrm;
    __nv_bfloat16 h, lw;
    split_bf(nv, h, lw);
    size_t o = (size_t)l * PP + p;
    hi[o] = h;
    lo[o] = lw;
}

// ---------------- mma.sync GEMM ----------------
// C[M, Ntot] = (Ahi+Alo)[M,K] @ (Bhi+Blo)[Ntot,K]^T ; bf16x3 split, fp32 acc.
// CTA tile 128x128, K-chunk 64. 8 warps (4x2), warp tile 32x64.
// 3-stage cp.async pipeline: loads run 2 chunks ahead of compute.
// Rows are 128B (64 bf16); chunk swizzle: 16B chunk c stored at c ^ (row & 7).
#define TILE_B 16384
#define STAGE_B 65536
#define NSTAGE 3
#define SMEM_TOTAL (256 + NSTAGE * STAGE_B)

template <int MODE>
__global__ __launch_bounds__(256, 1) void mma_gemm_kernel(
    const __nv_bfloat16* __restrict__ Ahi, const __nv_bfloat16* __restrict__ Alo,
    const __nv_bfloat16* __restrict__ Bhi, const __nv_bfloat16* __restrict__ Blo,
    int K, int Ntot,
    const float* __restrict__ s, const float* __restrict__ t,
    float* __restrict__ Cf, __nv_bfloat16* __restrict__ Chi, __nv_bfloat16* __restrict__ Clo)
{
    extern __shared__ char smem_raw[];
    uint32_t sb = (smem_u32(smem_raw) + 127u) & ~127u;

    const int tid = threadIdx.x;
    const int lane = tid & 31;
    const int warp = tid >> 5;
    const int warpM = (warp & 3) * 32;
    const int warpN = (warp >> 2) * 64;

    const int rowA0 = blockIdx.y * 128;
    const int rowB0 = blockIdx.x * 128;
    const int nch = K >> 6;

    // cp.async mapping: 1024 16B-chunks per tile, 4 per thread
    const int ldR = tid >> 1;                // row 0..127 (2 threads per row)
    const int ldC0 = (tid & 1) * 4;          // chunk 0..3 or 4..7 base

    // ldmatrix lane mapping
    const int g = lane >> 3, r8 = lane & 7;
    const int mA = warpM + ((g & 1) << 3) + r8;   // + mt*16
    const int cAg = g >> 1;
    const int swzA = mA & 7;
    const int nB = warpN + ((g >> 1) << 3) + r8;  // + ng*16
    const int cBg = g & 1;
    const int swzB = nB & 7;

    float acc[2][8][4];
#pragma unroll
    for (int mt = 0; mt < 2; mt++)
#pragma unroll
        for (int nt = 0; nt < 8; nt++)
#pragma unroll
            for (int i = 0; i < 4; i++) acc[mt][nt][i] = 0.0f;

    auto load_stage = [&](int stage, int k0) {
        uint32_t st = sb + (uint32_t)stage * STAGE_B;
        const __nv_bfloat16* srcs[4] = {Ahi, Alo, Bhi, Blo};
#pragma unroll
        for (int tidx = 0; tidx < 4; tidx++) {
            const __nv_bfloat16* base = srcs[tidx];
            int row0 = (tidx < 2) ? rowA0 : rowB0;
            uint32_t tb = st + (uint32_t)tidx * TILE_B;
#pragma unroll
            for (int c = 0; c < 4; c++) {
                int ch = ldC0 + c;
                const __nv_bfloat16* src = base + (size_t)(row0 + ldR) * K + (k0 + ch * 8);
                uint32_t dst = tb + (uint32_t)(ldR * 128 + ((ch ^ (ldR & 7)) << 4));
                cpasync16(dst, src);
            }
        }
    };

    // prologue: stage 0 and 1
    load_stage(0, 0);
    CP_COMMIT();
    if (nch > 1) load_stage(1, 64);
    CP_COMMIT();

    for (int ck = 0; ck < nch; ck++) {
        if (ck + 1 < nch) {
            asm volatile("cp.async.wait_group 1;" ::: "memory");
        } else {
            asm volatile("cp.async.wait_group 0;" ::: "memory");
        }
        __syncthreads();   // stage (ck%3) ready for all warps; all warps done with stage ((ck+2)%3)

        // prefetch 2 chunks ahead into the stage compute finished last iteration
        if (ck + 2 < nch) load_stage((ck + 2) % NSTAGE, (ck + 2) << 6);
        CP_COMMIT();

        uint32_t stA_hi = sb + (uint32_t)(ck % NSTAGE) * STAGE_B;
        uint32_t stA_lo = stA_hi + TILE_B;
        uint32_t stB_hi = stA_hi + 2 * TILE_B;
        uint32_t stB_lo = stA_hi + 3 * TILE_B;

#pragma unroll
        for (int ks = 0; ks < 4; ks++) {
            uint32_t ah[2][4], al[2][4], bh[4][4], bl[4][4];
#pragma unroll
            for (int mt = 0; mt < 2; mt++) {
                uint32_t roff = (uint32_t)((mA + mt * 16) * 128 +
                                           ((((ks << 1) + cAg) ^ swzA) << 4));
                ldsm4(ah[mt][0], ah[mt][1], ah[mt][2], ah[mt][3], stA_hi + roff);
                ldsm4(al[mt][0], al[mt][1], al[mt][2], al[mt][3], stA_lo + roff);
            }
#pragma unroll
            for (int ng = 0; ng < 4; ng++) {
                uint32_t roff = (uint32_t)((nB + ng * 16) * 128 +
                                           ((((ks << 1) + cBg) ^ swzB) << 4));
                ldsm4(bh[ng][0], bh[ng][1], bh[ng][2], bh[ng][3], stB_hi + roff);
                ldsm4(bl[ng][0], bl[ng][1], bl[ng][2], bl[ng][3], stB_lo + roff);
            }
            // term pass 1: hi*hi — 16 independent accumulators in a row
#pragma unroll
            for (int mt = 0; mt < 2; mt++)
#pragma unroll
                for (int nt = 0; nt < 8; nt++)
                    mma16816(acc[mt][nt], ah[mt], &bh[nt >> 1][(nt & 1) << 1]);
            // term pass 2: hi*lo
#pragma unroll
            for (int mt = 0; mt < 2; mt++)
#pragma unroll
                for (int nt = 0; nt < 8; nt++)
                    mma16816(acc[mt][nt], ah[mt], &bl[nt >> 1][(nt & 1) << 1]);
            // term pass 3: lo*hi
#pragma unroll
            for (int mt = 0; mt < 2; mt++)
#pragma unroll
                for (int nt = 0; nt < 8; nt++)
                    mma16816(acc[mt][nt], al[mt], &bh[nt >> 1][(nt & 1) << 1]);
        }
    }

    // ---- epilogue ----
    const int gid = lane >> 2, tig = lane & 3;
#pragma unroll
    for (int mt = 0; mt < 2; mt++) {
        int row0 = rowA0 + warpM + mt * 16 + gid;
#pragma unroll
        for (int nt = 0; nt < 8; nt++) {
            int n0 = rowB0 + warpN + nt * 8 + tig * 2;
            float c0 = acc[mt][nt][0], c1 = acc[mt][nt][1];
            float c2 = acc[mt][nt][2], c3 = acc[mt][nt][3];
            if (MODE == 0) {
                float s0 = s[n0], s1v = s[n0 + 1], t0 = t[n0], t1v = t[n0 + 1];
                float v0 = c0 * s0 + t0; v0 = (v0 >= 0.f) ? v0 : LRELU_SLOPE * v0;
                float v1 = c1 * s1v + t1v; v1 = (v1 >= 0.f) ? v1 : LRELU_SLOPE * v1;
                float v2 = c2 * s0 + t0; v2 = (v2 >= 0.f) ? v2 : LRELU_SLOPE * v2;
                float v3 = c3 * s1v + t1v; v3 = (v3 >= 0.f) ? v3 : LRELU_SLOPE * v3;
                __nv_bfloat16 h0, l0, h1, l1;
                split_bf(v0, h0, l0); split_bf(v1, h1, l1);
                __nv_bfloat162 hp; hp.x = h0; hp.y = h1;
                __nv_bfloat162 lp; lp.x = l0; lp.y = l1;
                *reinterpret_cast<__nv_bfloat162*>(Chi + (size_t)row0 * Ntot + n0) = hp;
                *reinterpret_cast<__nv_bfloat162*>(Clo + (size_t)row0 * Ntot + n0) = lp;
                split_bf(v2, h0, l0); split_bf(v3, h1, l1);
                hp.x = h0; hp.y = h1; lp.x = l0; lp.y = l1;
                *reinterpret_cast<__nv_bfloat162*>(Chi + (size_t)(row0 + 8) * Ntot + n0) = hp;
                *reinterpret_cast<__nv_bfloat162*>(Clo + (size_t)(row0 + 8) * Ntot + n0) = lp;
            } else {
                if (MODE == 1) {
                    float t0 = t[n0], t1v = t[n0 + 1];
                    c0 += t0; c1 += t1v; c2 += t0; c3 += t1v;
                }
                *reinterpret_cast<float2*>(Cf + (size_t)row0 * Ntot + n0) = make_float2(c0, c1);
                *reinterpret_cast<float2*>(Cf + (size_t)(row0 + 8) * Ntot + n0) = make_float2(c2, c3);
            }
        }
    }
}

// ---------------- sparsemax (P=512 per row) + split-bf16 output ----------------
__global__ __launch_bounds__(PP) void sparsemax_kernel(const float* __restrict__ logits,
                                                       float* __restrict__ a,
                                                       __nv_bfloat16* __restrict__ ahi,
                                                       __nv_bfloat16* __restrict__ alo) {
    __shared__ float zs[PP];
    __shared__ float cs[PP];
    __shared__ float red[PP];
    __shared__ int redi[PP];

    int row = blockIdx.x, tid = threadIdx.x;
    float v = logits[(size_t)row * PP + tid];

    red[tid] = v;
    __syncthreads();
    for (int o = PP / 2; o > 0; o >>= 1) {
        if (tid < o) red[tid] = fmaxf(red[tid], red[tid + o]);
        __syncthreads();
    }
    float zmax = red[0];
    __syncthreads();

    float zi = v - zmax;
    zs[tid] = zi;
    __syncthreads();

    for (int k = 2; k <= PP; k <<= 1) {
        for (int j = k >> 1; j > 0; j >>= 1) {
            int ixj = tid ^ j;
            if (ixj > tid) {
                float x0 = zs[tid], x1 = zs[ixj];
                bool desc = ((tid & k) == 0);
                if ((x0 < x1) == desc) { zs[tid] = x1; zs[ixj] = x0; }
            }
            __syncthreads();
        }
    }

    cs[tid] = zs[tid];
    __syncthreads();
    for (int o = 1; o < PP; o <<= 1) {
        float prev = (tid >= o) ? cs[tid - o] : 0.0f;
        float cur = cs[tid];
        __syncthreads();
        cs[tid] = cur + prev;
        __syncthreads();
    }

    redi[tid] = (1.0f + (float)(tid + 1) * zs[tid] > cs[tid]) ? 1 : 0;
    __syncthreads();
    for (int o = PP / 2; o > 0; o >>= 1) {
        if (tid < o) redi[tid] += redi[tid + o];
        __syncthreads();
    }
    int ssn = redi[0];
    if (ssn < 1) ssn = 1;
    float tau = (cs[ssn - 1] - 1.0f) / (float)ssn;

    float ai = zi - tau;
    ai = (ai > 0.0f) ? ai : 0.0f;

    red[tid] = ai;
    __syncthreads();
    for (int o = PP / 2; o > 0; o >>= 1) {
        if (tid < o) red[tid] += red[tid + o];
        __syncthreads();
    }
    float ssum = red[0];
    ssum = (ssum > 1e-8f) ? ssum : 1e-8f;
    float av = ai / ssum;
    size_t idx = (size_t)row * PP + tid;
    a[idx] = av;
    __nv_bfloat16 h, l;
    split_bf(av, h, l);
    ahi[idx] = h;
    alo[idx] = l;
}

// ---------------- launch ----------------
extern "C" void kernel_launch(void* const* d_in, const int* in_sizes, int n_in,
                              void* d_out, int out_size) {
    const float* x   = (const float*)d_in[0];
    const float* W1  = (const float*)d_in[1];
    const float* b1  = (const float*)d_in[2];
    const float* g1  = (const float*)d_in[3];
    const float* be1 = (const float*)d_in[4];
    const float* m1  = (const float*)d_in[5];
    const float* v1  = (const float*)d_in[6];
    const float* W2  = (const float*)d_in[7];
    const float* b2  = (const float*)d_in[8];
    const float* g2  = (const float*)d_in[9];
    const float* be2 = (const float*)d_in[10];
    const float* m2  = (const float*)d_in[11];
    const float* v2  = (const float*)d_in[12];
    const float* Wl  = (const float*)d_in[13];
    const float* bl  = (const float*)d_in[14];
    const float* basis = (const float*)d_in[15];

    float* out = (float*)d_out;
    float* a_out      = out;
    float* z_out      = out + (size_t)BB * PP;
    float* logits_out = out + (size_t)BB * PP + (size_t)BB * LL;

    __nv_bfloat16 *xhi, *xlo, *h1hi, *h1lo, *h2hi, *h2lo, *ahi, *alo;
    __nv_bfloat16 *w1thi, *w1tlo, *w2thi, *w2tlo, *wlthi, *wltlo, *nbthi, *nbtlo;
    float *s1, *t1, *s2, *t2;
    cudaGetSymbolAddress((void**)&xhi, g_xhi);
    cudaGetSymbolAddress((void**)&xlo, g_xlo);
    cudaGetSymbolAddress((void**)&h1hi, g_h1hi);
    cudaGetSymbolAddress((void**)&h1lo, g_h1lo);
    cudaGetSymbolAddress((void**)&h2hi, g_h2hi);
    cudaGetSymbolAddress((void**)&h2lo, g_h2lo);
    cudaGetSymbolAddress((void**)&ahi, g_ahi);
    cudaGetSymbolAddress((void**)&alo, g_alo);
    cudaGetSymbolAddress((void**)&w1thi, g_w1thi);
    cudaGetSymbolAddress((void**)&w1tlo, g_w1tlo);
    cudaGetSymbolAddress((void**)&w2thi, g_w2thi);
    cudaGetSymbolAddress((void**)&w2tlo, g_w2tlo);
    cudaGetSymbolAddress((void**)&wlthi, g_wlthi);
    cudaGetSymbolAddress((void**)&wltlo, g_wltlo);
    cudaGetSymbolAddress((void**)&nbthi, g_nbthi);
    cudaGetSymbolAddress((void**)&nbtlo, g_nbtlo);
    cudaGetSymbolAddress((void**)&s1, g_s1);
    cudaGetSymbolAddress((void**)&t1, g_t1);
    cudaGetSymbolAddress((void**)&s2, g_s2);
    cudaGetSymbolAddress((void**)&t2, g_t2);

    cudaFuncSetAttribute(mma_gemm_kernel<0>, cudaFuncAttributeMaxDynamicSharedMemorySize, SMEM_TOTAL);
    cudaFuncSetAttribute(mma_gemm_kernel<1>, cudaFuncAttributeMaxDynamicSharedMemorySize, SMEM_TOTAL);
    cudaFuncSetAttribute(mma_gemm_kernel<2>, cudaFuncAttributeMaxDynamicSharedMemorySize, SMEM_TOTAL);

    // prep
    prep_scale_kernel<<<(HH1 + 255) / 256, 256>>>(b1, g1, be1, m1, v1, s1, t1, HH1);
    prep_scale_kernel<<<(HH2 + 255) / 256, 256>>>(b2, g2, be2, m2, v2, s2, t2, HH2);
    transpose_split_kernel<<<dim3(HH1 / 32, DD / 32), dim3(32, 8)>>>(W1, w1thi, w1tlo, DD, HH1);
    transpose_split_kernel<<<dim3(HH2 / 32, HH1 / 32), dim3(32, 8)>>>(W2, w2thi, w2tlo, HH1, HH2);
    transpose_split_kernel<<<dim3(PP / 32, HH2 / 32), dim3(32, 8)>>>(Wl, wlthi, wltlo, HH2, PP);
    nbt_kernel<<<PP, LL>>>(basis, nbthi, nbtlo);
    {
        size_t n4 = (size_t)BB * DD / 4;
        split_kernel<<<(unsigned)((n4 + 255) / 256), 256>>>(x, xhi, xlo, n4);
    }

    // GEMM 1: h1 = lrelu(BN(x @ W1))
    mma_gemm_kernel<0><<<dim3(HH1 / 128, BB / 128), 256, SMEM_TOTAL>>>(
        xhi, xlo, w1thi, w1tlo, DD, HH1, s1, t1, nullptr, h1hi, h1lo);
    // GEMM 2: h2 = lrelu(BN(h1 @ W2))
    mma_gemm_kernel<0><<<dim3(HH2 / 128, BB / 128), 256, SMEM_TOTAL>>>(
        h1hi, h1lo, w2thi, w2tlo, HH1, HH2, s2, t2, nullptr, h2hi, h2lo);
    // GEMM 3: logits = h2 @ Wl + bl
    mma_gemm_kernel<1><<<dim3(PP / 128, BB / 128), 256, SMEM_TOTAL>>>(
        h2hi, h2lo, wlthi, wltlo, HH2, PP, nullptr, bl, logits_out, nullptr, nullptr);
    // sparsemax
    sparsemax_kernel<<<BB, PP>>>(logits_out, a_out, ahi, alo);
    // GEMM 4: z = a @ nb
    mma_gemm_kernel<2><<<dim3(LL / 128, BB / 128), 256, SMEM_TOTAL>>>(
        ahi, alo, nbthi, nbtlo, PP, LL, nullptr, nullptr, z_out, nullptr, nullptr);
}